// round 8
// baseline (speedup 1.0000x reference)
#include <cuda_runtime.h>
#include <float.h>

// ROI max pooling, 2-pass (fused pyramid + trivial gather).
// feat: [B=8, H=50, W=50, C=256] fp32 NHWC; rois: [N,5] (img,x1,y1,x2,y2) incl.
// Dataset ROIs are 28x28 with 7x7 pooling -> each bin = aligned 4x4 window:
//   out[roi,br,bc] = max feat[img, y1+4br..+3, x1+4bc..+3].
// Pass A (fused): Vm[b,y,x] = max_{4x4 window} feat[b, y..y+3, x..x+3]
// Pass B: out[roi,br,bc] = Vm[img, y1+4br, x1+4bc]
//   one CTA per (roi, br), 448 threads; each thread = 1 load + 1 store.
// General fallback (non-28x28 ROI): direct loop over feat.

#define FH 50
#define FW 50
#define CCH 256
#define PH 7
#define PW 7
#define HX 47               // FW - 3 (valid window origins)
#define HY 47
#define TW 4                // Vm tile width per CTA
#define TH 4                // Vm tile height per CTA
#define NXC 12              // ceil(47/4)
#define NYC 12

__device__ float g_vm[8 * HY * HX * CCH];   // 18.1 MB

__device__ __forceinline__ float4 vmax2(float4 a, float4 b) {
    float4 r;
    r.x = fmaxf(a.x, b.x);
    r.y = fmaxf(a.y, b.y);
    r.z = fmaxf(a.z, b.z);
    r.w = fmaxf(a.w, b.w);
    return r;
}

// Fused H+V window-4 max: one CTA = (b, 4x4 output tile), 64 threads x 4ch.
// Thread-private smem staging (no __syncthreads needed).
__global__ __launch_bounds__(64)
void hvmax_kernel(const float* __restrict__ feat)
{
    __shared__ float4 hs[7][TW][64];        // [in-row][out-col][thread] = 28 KB

    const int id = blockIdx.x;              // ((b*NYC)+yc)*NXC + xc
    const int xc = id % NXC;
    const int t1 = id / NXC;
    const int yc = t1 % NYC;
    const int b  = t1 / NYC;
    const int x0 = xc * TW;
    const int y0 = yc * TH;
    const int tid  = threadIdx.x;
    const int coff = tid * 4;

    const float4 NEG = make_float4(-FLT_MAX, -FLT_MAX, -FLT_MAX, -FLT_MAX);

    // Phase 1: per input row, 7 loads -> 4 horizontal window maxes -> smem.
    #pragma unroll
    for (int j = 0; j < 7; ++j) {
        const int y = y0 + j;
        float4 v[7];
        if (y < FH) {
            const float* rowp = feat + ((size_t)(b * FH + y) * FW) * CCH + coff;
            #pragma unroll
            for (int k = 0; k < 7; ++k) {
                const int x = x0 + k;
                v[k] = (x < FW)
                     ? *reinterpret_cast<const float4*>(rowp + (size_t)x * CCH)
                     : NEG;
            }
        } else {
            #pragma unroll
            for (int k = 0; k < 7; ++k) v[k] = NEG;
        }
        const float4 m01 = vmax2(v[0], v[1]);
        const float4 m23 = vmax2(v[2], v[3]);
        const float4 m12 = vmax2(v[1], v[2]);
        const float4 m34 = vmax2(v[3], v[4]);
        const float4 m45 = vmax2(v[4], v[5]);
        const float4 m56 = vmax2(v[5], v[6]);
        hs[j][0][tid] = vmax2(m01, m23);
        hs[j][1][tid] = vmax2(m12, m34);
        hs[j][2][tid] = vmax2(m23, m45);
        hs[j][3][tid] = vmax2(m34, m56);
    }

    // Phase 2: vertical window-4 max over staged rows (own slots only).
    #pragma unroll
    for (int r = 0; r < TH; ++r) {
        const int yo = y0 + r;
        if (yo >= HY) continue;
        float* outp = g_vm + (((size_t)b * HY + yo) * HX) * CCH + coff;
        #pragma unroll
        for (int c = 0; c < TW; ++c) {
            const int xo = x0 + c;
            if (xo >= HX) continue;
            const float4 m = vmax2(vmax2(hs[r][c][tid],     hs[r + 1][c][tid]),
                                   vmax2(hs[r + 2][c][tid], hs[r + 3][c][tid]));
            *reinterpret_cast<float4*>(outp + (size_t)xo * CCH) = m;
        }
    }
}

// Gather: one CTA per (roi, br), 448 threads = 7 bc x 64 channel-slots.
// Fast path: each thread does exactly 1 Vm load + 1 store.
__global__ __launch_bounds__(448)
void gather_kernel(const float* __restrict__ feat,
                   const int*   __restrict__ rois,
                   float*       __restrict__ out)
{
    const int roi = blockIdx.x / PH;
    const int br  = blockIdx.x - roi * PH;

    const int t    = threadIdx.x;
    const int bc   = t >> 6;                 // 0..6
    const int coff = (t & 63) * 4;           // channel offset

    const int* r = rois + roi * 5;
    const int img = r[0];
    const int x1  = r[1];
    const int y1  = r[2];
    const int x2  = r[3];
    const int y2  = r[4];
    const int roi_h = y2 - y1 + 1;
    const int roi_w = x2 - x1 + 1;

    float* o = out + ((size_t)((roi * PH + br) * PW + bc)) * CCH + coff;

    if (roi_h == 28 && roi_w == 28) {
        const int yy = y1 + 4 * br;
        const int xx = x1 + 4 * bc;
        const float4 v = *reinterpret_cast<const float4*>(
            g_vm + (((size_t)img * HY + yy) * HX + xx) * CCH + coff);
        *reinterpret_cast<float4*>(o) = v;
    } else {
        // General fallback: direct max over this bin's pixel range in feat.
        const int rs = (br * roi_h + PH - 1) / PH;
        const int re = (br == PH - 1) ? roi_h : ((br + 1) * roi_h + PH - 1) / PH;
        const int cs = (bc * roi_w + PW - 1) / PW;
        const int ce = (bc == PW - 1) ? roi_w : ((bc + 1) * roi_w + PW - 1) / PW;
        const float* base = feat
            + (((size_t)img * FH + (size_t)y1) * FW + (size_t)x1) * CCH + coff;
        float4 m = make_float4(-FLT_MAX, -FLT_MAX, -FLT_MAX, -FLT_MAX);
        for (int y = rs; y < re; ++y) {
            const float* rowp = base + (size_t)y * (FW * CCH);
            for (int x = cs; x < ce; ++x) {
                const float4 v = *reinterpret_cast<const float4*>(rowp + (size_t)x * CCH);
                m.x = fmaxf(m.x, v.x); m.y = fmaxf(m.y, v.y);
                m.z = fmaxf(m.z, v.z); m.w = fmaxf(m.w, v.w);
            }
        }
        *reinterpret_cast<float4*>(o) = m;
    }
}

extern "C" void kernel_launch(void* const* d_in, const int* in_sizes, int n_in,
                              void* d_out, int out_size)
{
    const float* feat = (const float*)d_in[0];
    const int*   rois = (const int*)d_in[1];
    const int n_rois = in_sizes[1] / 5;
    float* out = (float*)d_out;

    hvmax_kernel<<<8 * NYC * NXC, 64>>>(feat);
    gather_kernel<<<n_rois * PH, 448>>>(feat, rois, out);
}

// round 9
// speedup vs baseline: 1.1550x; 1.1550x over previous
#include <cuda_runtime.h>
#include <float.h>

// ROI max pooling, SINGLE kernel.
// feat: [B=8, H=50, W=50, C=256] fp32 NHWC; rois: [N,5] (img,x1,y1,x2,y2) incl.
// Dataset ROIs are 28x28 with 7x7 pooling -> each bin = aligned 4x4 window at
// Vm position (y1+4br, x1+4bc). Tiles of 4x4 Vm positions partition the grid,
// so each tile CTA scans the ROI list, finds the bins that land in its tile,
// computes their 4x4 window max from staged horizontal maxes, and writes out.
// Extra per-ROI CTAs handle any non-28x28 ROI via the general path.

#define FH 50
#define FW 50
#define CCH 256
#define PH 7
#define PW 7
#define NXC 12              // tiles per row: ceil(47/4)
#define NYC 12
#define NTILES (8 * NYC * NXC)   // 1152
#define MAXM 384            // match-list capacity per tile

__device__ __forceinline__ float4 vmax2(float4 a, float4 b) {
    float4 r;
    r.x = fmaxf(a.x, b.x);
    r.y = fmaxf(a.y, b.y);
    r.z = fmaxf(a.z, b.z);
    r.w = fmaxf(a.w, b.w);
    return r;
}

__global__ __launch_bounds__(64)
void roi_pool_fused(const float* __restrict__ feat,
                    const int*   __restrict__ rois,
                    float*       __restrict__ out,
                    int n_rois)
{
    const int tid  = threadIdx.x;
    const int coff = tid * 4;

    // ---------- fallback CTAs: one per ROI, only act on non-28x28 ----------
    if (blockIdx.x >= NTILES) {
        const int roi = blockIdx.x - NTILES;
        if (roi >= n_rois) return;
        const int* r = rois + roi * 5;
        const int img = r[0], x1 = r[1], y1 = r[2], x2 = r[3], y2 = r[4];
        const int roi_h = y2 - y1 + 1;
        const int roi_w = x2 - x1 + 1;
        if (roi_h == 28 && roi_w == 28) return;   // handled by tile CTAs

        const float* base = feat
            + (((size_t)img * FH + (size_t)y1) * FW + (size_t)x1) * CCH + coff;
        for (int br = 0; br < PH; ++br) {
            const int rs = (br * roi_h + PH - 1) / PH;
            const int re = (br == PH - 1) ? roi_h
                                          : ((br + 1) * roi_h + PH - 1) / PH;
            for (int bc = 0; bc < PW; ++bc) {
                const int cs = (bc * roi_w + PW - 1) / PW;
                const int ce = (bc == PW - 1) ? roi_w
                                              : ((bc + 1) * roi_w + PW - 1) / PW;
                float4 m = make_float4(-FLT_MAX, -FLT_MAX, -FLT_MAX, -FLT_MAX);
                for (int y = rs; y < re; ++y) {
                    const float* rowp = base + (size_t)y * (FW * CCH);
                    for (int x = cs; x < ce; ++x) {
                        const float4 v =
                            *reinterpret_cast<const float4*>(rowp + (size_t)x * CCH);
                        m.x = fmaxf(m.x, v.x); m.y = fmaxf(m.y, v.y);
                        m.z = fmaxf(m.z, v.z); m.w = fmaxf(m.w, v.w);
                    }
                }
                *reinterpret_cast<float4*>(
                    out + ((size_t)((roi * PH + br) * PW + bc)) * CCH + coff) = m;
            }
        }
        return;
    }

    // ---------------------- tile CTAs ----------------------
    __shared__ float4 hs[7][4][64];      // staged horizontal 4-maxes, 28 KB
    __shared__ int    s_roi[MAXM];
    __shared__ int    s_pk[MAXM];        // packed br|bc|yloc|xloc
    __shared__ int    s_cnt;

    const int id = blockIdx.x;           // ((b*NYC)+ty)*NXC + tx
    const int tx = id % NXC;
    const int t1 = id / NXC;
    const int ty = t1 % NYC;
    const int b  = t1 / NYC;
    const int x0 = tx * 4;
    const int y0 = ty * 4;

    if (tid == 0) s_cnt = 0;

    const float4 NEG = make_float4(-FLT_MAX, -FLT_MAX, -FLT_MAX, -FLT_MAX);

    // Phase 1: stage horizontal window-4 maxes for 7 input rows.
    #pragma unroll
    for (int j = 0; j < 7; ++j) {
        const int y = y0 + j;
        float4 v[7];
        if (y < FH) {
            const float* rowp = feat + ((size_t)(b * FH + y) * FW) * CCH + coff;
            #pragma unroll
            for (int k = 0; k < 7; ++k) {
                const int x = x0 + k;
                v[k] = (x < FW)
                     ? *reinterpret_cast<const float4*>(rowp + (size_t)x * CCH)
                     : NEG;
            }
        } else {
            #pragma unroll
            for (int k = 0; k < 7; ++k) v[k] = NEG;
        }
        const float4 m01 = vmax2(v[0], v[1]);
        const float4 m23 = vmax2(v[2], v[3]);
        const float4 m12 = vmax2(v[1], v[2]);
        const float4 m34 = vmax2(v[3], v[4]);
        const float4 m45 = vmax2(v[4], v[5]);
        const float4 m56 = vmax2(v[5], v[6]);
        hs[j][0][tid] = vmax2(m01, m23);
        hs[j][1][tid] = vmax2(m12, m34);
        hs[j][2][tid] = vmax2(m23, m45);
        hs[j][3][tid] = vmax2(m34, m56);
    }

    __syncthreads();   // orders s_cnt=0 before scan's atomicAdd

    // Phase 2: scan ROIs; each thread handles rois tid, tid+64, ...
    for (int roi = tid; roi < n_rois; roi += 64) {
        const int* r = rois + roi * 5;
        const int img = r[0], x1 = r[1], y1 = r[2], x2 = r[3], y2 = r[4];
        if (img != b) continue;
        if (y2 - y1 != 27 || x2 - x1 != 27) continue;  // fallback CTA handles
        const int dy = y0 - y1;
        const int dx = x0 - x1;
        if (dy < -3 || dy > 24 || dx < -3 || dx > 24) continue;
        const int br = (dy + 3) >> 2;      // unique bin row landing in tile
        const int bc = (dx + 3) >> 2;
        const int yloc = 4 * br - dy;      // 0..3
        const int xloc = 4 * bc - dx;      // 0..3
        const int slot = atomicAdd(&s_cnt, 1);
        if (slot < MAXM) {
            s_roi[slot] = roi;
            s_pk[slot]  = (br << 12) | (bc << 8) | (yloc << 4) | xloc;
        }
    }

    __syncthreads();

    // Phase 3: scatter. For each match, vertical 4-max over own staged slots.
    const int cnt = min(s_cnt, MAXM);
    for (int i = 0; i < cnt; ++i) {
        const int roi = s_roi[i];
        const int pk  = s_pk[i];
        const int br   = (pk >> 12) & 0xF;
        const int bc   = (pk >> 8)  & 0xF;
        const int yloc = (pk >> 4)  & 0xF;
        const int xloc =  pk        & 0xF;
        const float4 m = vmax2(vmax2(hs[yloc][xloc][tid],
                                     hs[yloc + 1][xloc][tid]),
                               vmax2(hs[yloc + 2][xloc][tid],
                                     hs[yloc + 3][xloc][tid]));
        *reinterpret_cast<float4*>(
            out + ((size_t)((roi * PH + br) * PW + bc)) * CCH + coff) = m;
    }
}

extern "C" void kernel_launch(void* const* d_in, const int* in_sizes, int n_in,
                              void* d_out, int out_size)
{
    const float* feat = (const float*)d_in[0];
    const int*   rois = (const int*)d_in[1];
    const int n_rois = in_sizes[1] / 5;
    float* out = (float*)d_out;

    roi_pool_fused<<<NTILES + n_rois, 64>>>(feat, rois, out, n_rois);
}

// round 10
// speedup vs baseline: 1.6190x; 1.4018x over previous
#include <cuda_runtime.h>
#include <float.h>

// ROI max pooling, SINGLE kernel, occupancy-tuned.
// feat: [B=8, H=50, W=50, C=256] fp32 NHWC; rois: [N,5] (img,x1,y1,x2,y2) incl.
// Dataset ROIs are 28x28 with 7x7 pooling -> each bin = aligned 4x4 window at
// position (y1+4br, x1+4bc). 4x4 tiles partition the 47x47 window-origin grid;
// each tile CTA streams 7 input rows, keeps the 4x4 window maxes in registers,
// parks them in smem, scans the ROI list for consumers, and scatters to out.
// Extra per-ROI CTAs handle any non-28x28 ROI via the general path.

#define FH 50
#define FW 50
#define CCH 256
#define PH 7
#define PW 7
#define NXC 12                   // tiles per row: ceil(47/4)
#define NYC 12
#define NTILES (8 * NYC * NXC)   // 1152
#define MAXM 256                 // match-list capacity per tile

__device__ __forceinline__ float2 fmax2(float2 a, float2 b) {
    float2 r;
    r.x = fmaxf(a.x, b.x);
    r.y = fmaxf(a.y, b.y);
    return r;
}

__global__ __launch_bounds__(128, 8)
void roi_pool_fused(const float* __restrict__ feat,
                    const int*   __restrict__ rois,
                    float*       __restrict__ out,
                    int n_rois)
{
    const int tid  = threadIdx.x;        // 0..127
    const int coff = tid * 2;            // 2 channels per thread

    // ---------- fallback CTAs: one per ROI, only act on non-28x28 ----------
    if (blockIdx.x >= NTILES) {
        const int roi = blockIdx.x - NTILES;
        if (roi >= n_rois) return;
        const int* r = rois + roi * 5;
        const int img = r[0], x1 = r[1], y1 = r[2], x2 = r[3], y2 = r[4];
        const int roi_h = y2 - y1 + 1;
        const int roi_w = x2 - x1 + 1;
        if (roi_h == 28 && roi_w == 28) return;   // handled by tile CTAs

        const float* base = feat
            + (((size_t)img * FH + (size_t)y1) * FW + (size_t)x1) * CCH + coff;
        for (int br = 0; br < PH; ++br) {
            const int rs = (br * roi_h + PH - 1) / PH;
            const int re = (br == PH - 1) ? roi_h
                                          : ((br + 1) * roi_h + PH - 1) / PH;
            for (int bc = 0; bc < PW; ++bc) {
                const int cs = (bc * roi_w + PW - 1) / PW;
                const int ce = (bc == PW - 1) ? roi_w
                                              : ((bc + 1) * roi_w + PW - 1) / PW;
                float2 m = make_float2(-FLT_MAX, -FLT_MAX);
                for (int y = rs; y < re; ++y) {
                    const float* rowp = base + (size_t)y * (FW * CCH);
                    for (int x = cs; x < ce; ++x) {
                        const float2 v =
                            *reinterpret_cast<const float2*>(rowp + (size_t)x * CCH);
                        m = fmax2(m, v);
                    }
                }
                *reinterpret_cast<float2*>(
                    out + ((size_t)((roi * PH + br) * PW + bc)) * CCH + coff) = m;
            }
        }
        return;
    }

    // ---------------------- tile CTAs ----------------------
    __shared__ float2 vm[4][4][128];     // finished 4x4 window maxes, 16 KB
    __shared__ int    s_roi[MAXM];
    __shared__ int    s_pk[MAXM];        // packed br|bc|yloc|xloc
    __shared__ int    s_cnt;

    const int id = blockIdx.x;           // ((b*NYC)+ty)*NXC + tx
    const int tx = id % NXC;
    const int t1 = id / NXC;
    const int ty = t1 % NYC;
    const int b  = t1 / NYC;
    const int x0 = tx * 4;
    const int y0 = ty * 4;

    if (tid == 0) s_cnt = 0;

    const float2 NEG = make_float2(-FLT_MAX, -FLT_MAX);

    // Streaming: per input row j, 7 loads -> 4 horizontal window maxes ->
    // update the vertical accumulators of output rows r in [j-3, j] & [0,3].
    float2 acc[4][4];
    #pragma unroll
    for (int r = 0; r < 4; ++r)
        #pragma unroll
        for (int c = 0; c < 4; ++c)
            acc[r][c] = NEG;

    #pragma unroll
    for (int j = 0; j < 7; ++j) {
        const int y = y0 + j;
        float2 v[7];
        if (y < FH) {
            const float* rowp = feat + ((size_t)(b * FH + y) * FW) * CCH + coff;
            #pragma unroll
            for (int k = 0; k < 7; ++k) {
                const int x = x0 + k;
                v[k] = (x < FW)
                     ? *reinterpret_cast<const float2*>(rowp + (size_t)x * CCH)
                     : NEG;
            }
        } else {
            #pragma unroll
            for (int k = 0; k < 7; ++k) v[k] = NEG;
        }
        const float2 m01 = fmax2(v[0], v[1]);
        const float2 m12 = fmax2(v[1], v[2]);
        const float2 m23 = fmax2(v[2], v[3]);
        const float2 m34 = fmax2(v[3], v[4]);
        const float2 m45 = fmax2(v[4], v[5]);
        const float2 m56 = fmax2(v[5], v[6]);
        float2 h[4];
        h[0] = fmax2(m01, m23);
        h[1] = fmax2(m12, m34);
        h[2] = fmax2(m23, m45);
        h[3] = fmax2(m34, m56);

        #pragma unroll
        for (int r = 0; r < 4; ++r) {
            if (j >= r && j <= r + 3) {
                #pragma unroll
                for (int c = 0; c < 4; ++c)
                    acc[r][c] = fmax2(acc[r][c], h[c]);
            }
        }
    }

    // Park finished tile in smem for dynamically-indexed scatter reads.
    #pragma unroll
    for (int r = 0; r < 4; ++r)
        #pragma unroll
        for (int c = 0; c < 4; ++c)
            vm[r][c][tid] = acc[r][c];

    __syncthreads();   // orders s_cnt=0 before atomics; vm before scatter

    // Scan ROIs; each thread handles rois tid, tid+128, ...
    for (int roi = tid; roi < n_rois; roi += 128) {
        const int* r = rois + roi * 5;
        const int img = r[0], x1 = r[1], y1 = r[2], x2 = r[3], y2 = r[4];
        if (img != b) continue;
        if (y2 - y1 != 27 || x2 - x1 != 27) continue;  // fallback CTA handles
        const int dy = y0 - y1;
        const int dx = x0 - x1;
        if (dy < -3 || dy > 24 || dx < -3 || dx > 24) continue;
        const int br = (dy + 3) >> 2;      // unique bin row landing in tile
        const int bc = (dx + 3) >> 2;
        const int yloc = 4 * br - dy;      // 0..3
        const int xloc = 4 * bc - dx;      // 0..3
        const int slot = atomicAdd(&s_cnt, 1);
        if (slot < MAXM) {
            s_roi[slot] = roi;
            s_pk[slot]  = (br << 12) | (bc << 8) | (yloc << 4) | xloc;
        }
    }

    __syncthreads();

    // Scatter: every thread writes its 2 channels for each match.
    const int cnt = min(s_cnt, MAXM);
    for (int i = 0; i < cnt; ++i) {
        const int roi = s_roi[i];
        const int pk  = s_pk[i];
        const int br   = (pk >> 12) & 0xF;
        const int bc   = (pk >> 8)  & 0xF;
        const int yloc = (pk >> 4)  & 0xF;
        const int xloc =  pk        & 0xF;
        *reinterpret_cast<float2*>(
            out + ((size_t)((roi * PH + br) * PW + bc)) * CCH + coff)
            = vm[yloc][xloc][tid];
    }
}

extern "C" void kernel_launch(void* const* d_in, const int* in_sizes, int n_in,
                              void* d_out, int out_size)
{
    const float* feat = (const float*)d_in[0];
    const int*   rois = (const int*)d_in[1];
    const int n_rois = in_sizes[1] / 5;
    float* out = (float*)d_out;

    roi_pool_fused<<<NTILES + n_rois, 128>>>(feat, rois, out, n_rois);
}